// round 9
// baseline (speedup 1.0000x reference)
#include <cuda_runtime.h>

// ForceAggregation: out[m*D + r] = dot(hess[m][r][:], ns[m][:]),  D=300, M=2048.
// hess = 737 MB streamed once. Proven sweet spot: warp = row pair, depth-1
// rolled prefetch pipeline (~62 regs, ~43% occ). This round:
//  - 128-row tiles (3 tiles/mol: 128+128+44) -> uniform 8 pairs/warp in full
//    tiles, pipeline-drain fraction 25% -> 12.5%
//  - ns staged via SMEM once per block (L2 ns traffic 12.5% -> 1.6% of hess)
//  - #pragma unroll 1 keeps the loop rolled so regs stay ~62 (R8 showed full
//    unroll -> 80 regs -> occ cliff).

#define BLOCK_THREADS 256
#define D300 300

__device__ __forceinline__ float4 f4z() { return make_float4(0.f, 0.f, 0.f, 0.f); }

__device__ __forceinline__ float dot4(float4 a, float4 b, float acc) {
    acc = fmaf(a.x, b.x, acc);
    acc = fmaf(a.y, b.y, acc);
    acc = fmaf(a.z, b.z, acc);
    return fmaf(a.w, b.w, acc);
}

__global__ void __launch_bounds__(BLOCK_THREADS)
force_agg_300(const float* __restrict__ hess,
              const float* __restrict__ ns,
              float* __restrict__ out)
{
    constexpr int NCH = D300 / 4;            // 75 float4 chunks per row
    __shared__ __align__(16) float s_ns[D300];

    const int m    = blockIdx.x / 3;
    const int tile = blockIdx.x - m * 3;
    const int row0 = tile << 7;              // tiles: rows 0-127, 128-255, 256-299

    const int warp = threadIdx.x >> 5;
    const int lane = threadIdx.x & 31;

    // Stage ns_m into SMEM once per block (1.2 KB from L2 instead of 9.6 KB).
    if (threadIdx.x < NCH)
        ((float4*)s_ns)[threadIdx.x] =
            __ldg((const float4*)(ns + (size_t)m * D300) + threadIdx.x);
    __syncthreads();

    const bool has2 = (lane < NCH - 64);
    const float4* s4 = (const float4*)s_ns;
    const float4 n0 = s4[lane];
    const float4 n1 = s4[lane + 32];
    const float4 n2 = has2 ? s4[lane + 64] : f4z();

    const float* hbase = hess + (size_t)m * D300 * D300;
    float*       omol  = out + (size_t)m * D300;

    const int rend = (tile < 2) ? (row0 + 128) : D300;   // 44-row tail tile
    int r = row0 + (warp << 1);

    // ---- prologue: load current pair ----
    const float* hb = hbase + (size_t)r * D300;
    const float4* h0 = (const float4*)hb;
    const float4* h1 = (const float4*)(hb + D300);
    float4 a0 = __ldcs(h0 + lane);
    float4 b0 = __ldcs(h1 + lane);
    float4 a1 = __ldcs(h0 + lane + 32);
    float4 b1 = __ldcs(h1 + lane + 32);
    float4 a2 = f4z(), b2 = f4z();
    if (has2) { a2 = __ldcs(h0 + lane + 64); b2 = __ldcs(h1 + lane + 64); }

#pragma unroll 1
    for (; r < rend; r += 16) {
        // ---- prefetch next pair (in flight through the FMA/shuffle window) ----
        const int rn = r + 16;
        const bool more = (rn < rend);
        float4 pa0 = f4z(), pb0 = f4z(), pa1 = f4z(), pb1 = f4z(), pa2 = f4z(), pb2 = f4z();
        if (more) {
            const float* gb = hbase + (size_t)rn * D300;
            const float4* g0 = (const float4*)gb;
            const float4* g1 = (const float4*)(gb + D300);
            pa0 = __ldcs(g0 + lane);
            pb0 = __ldcs(g1 + lane);
            pa1 = __ldcs(g0 + lane + 32);
            pb1 = __ldcs(g1 + lane + 32);
            if (has2) { pa2 = __ldcs(g0 + lane + 64); pb2 = __ldcs(g1 + lane + 64); }
        }

        // ---- compute current pair ----
        float acc0 = dot4(a0, n0, 0.f);
        float acc1 = dot4(b0, n0, 0.f);
        acc0 = dot4(a1, n1, acc0);
        acc1 = dot4(b1, n1, acc1);
        acc0 = dot4(a2, n2, acc0);
        acc1 = dot4(b2, n2, acc1);

        // ---- 6-shuffle paired reduction: lane0 -> r, lane16 -> r+1 ----
        acc0 += __shfl_xor_sync(0xffffffffu, acc0, 16);
        acc1 += __shfl_xor_sync(0xffffffffu, acc1, 16);
        float v = (lane & 16) ? acc1 : acc0;
        v += __shfl_xor_sync(0xffffffffu, v, 8);
        v += __shfl_xor_sync(0xffffffffu, v, 4);
        v += __shfl_xor_sync(0xffffffffu, v, 2);
        v += __shfl_xor_sync(0xffffffffu, v, 1);
        if (lane == 0)       omol[r]     = v;
        else if (lane == 16) omol[r + 1] = v;

        // ---- rotate pipeline ----
        a0 = pa0; b0 = pb0; a1 = pa1; b1 = pb1; a2 = pa2; b2 = pb2;
    }
}

// Generic fallback for unexpected D (runtime loop bounds, smem-staged ns).
__global__ void __launch_bounds__(BLOCK_THREADS)
force_agg_generic(const float* __restrict__ hess,
                  const float* __restrict__ ns,
                  float* __restrict__ out,
                  int D, int tiles_per_mol, int rows_per_tile)
{
    extern __shared__ __align__(16) float s_ns[];

    const int m    = blockIdx.x / tiles_per_mol;
    const int tile = blockIdx.x - m * tiles_per_mol;
    const int row0 = tile * rows_per_tile;

    const float* nsm = ns + (size_t)m * D;
    const int nch = D >> 2;
    for (int i = threadIdx.x; i < nch; i += BLOCK_THREADS)
        ((float4*)s_ns)[i] = ((const float4*)nsm)[i];
    for (int i = nch * 4 + threadIdx.x; i < D; i += BLOCK_THREADS)
        s_ns[i] = nsm[i];
    __syncthreads();

    const int warp  = threadIdx.x >> 5;
    const int lane  = threadIdx.x & 31;
    const int nwrps = BLOCK_THREADS >> 5;

    const float4* s4    = (const float4*)s_ns;
    const float*  hbase = hess + (size_t)m * D * D;

    int rend = row0 + rows_per_tile;
    if (rend > D) rend = D;

    for (int r = row0 + warp; r < rend; r += nwrps) {
        const float4* hrow = (const float4*)(hbase + (size_t)r * D);
        float acc = 0.0f;
        for (int c = lane; c < nch; c += 32) {
            const float4 h = __ldcs(hrow + c);
            const float4 n = s4[c];
            acc = fmaf(h.x, n.x, acc);
            acc = fmaf(h.y, n.y, acc);
            acc = fmaf(h.z, n.z, acc);
            acc = fmaf(h.w, n.w, acc);
        }
        for (int c = nch * 4 + lane; c < D; c += 32)
            acc = fmaf(hbase[(size_t)r * D + c], s_ns[c], acc);
#pragma unroll
        for (int off = 16; off; off >>= 1)
            acc += __shfl_xor_sync(0xffffffffu, acc, off);
        if (lane == 0)
            out[(size_t)m * D + r] = acc;
    }
}

extern "C" void kernel_launch(void* const* d_in, const int* in_sizes, int n_in,
                              void* d_out, int out_size)
{
    // Input order: ns [M*N_AT,3] f32, hess [M*D,D] f32, idx_m i32, n_atoms [M] i32
    const float* ns   = (const float*)d_in[0];
    const float* hess = (const float*)d_in[1];
    float*       out  = (float*)d_out;

    const int M = in_sizes[3];
    const int D = (int)((long long)in_sizes[0] / M);

    if (D == 300) {
        force_agg_300<<<(unsigned)(M * 3), BLOCK_THREADS>>>(hess, ns, out);
    } else {
        const int rows = 64;
        const int tiles = (D + rows - 1) / rows;
        const size_t shmem = (size_t)((D + 3) / 4) * 16;
        force_agg_generic<<<(unsigned)(M * tiles), BLOCK_THREADS, shmem>>>(hess, ns, out, D, tiles, rows);
    }
}

// round 10
// speedup vs baseline: 1.0410x; 1.0410x over previous
#include <cuda_runtime.h>

// ForceAggregation: out[m*D + r] = dot(hess[m][r][:], ns[m][:]),  D=300, M=2048.
// hess = 737 MB streamed once. Converged macro-shape (R6): grid 10240,
// 64-row tiles, warp = row pair, rolled depth-1 prefetch pipeline, ~62 regs.
// This round's single change: full-tile warps own CONTIGUOUS 8-row stripes
// (pairs r, r+2, r+4, r+6) instead of strided pairs -> each warp emits one
// sequential 9.6 KB DRAM stream (row-buffer friendly). Tail tile unchanged.

#define ROWS_PER_BLOCK 64
#define BLOCK_THREADS 256
#define D300 300

__device__ __forceinline__ float4 f4z() { return make_float4(0.f, 0.f, 0.f, 0.f); }

__device__ __forceinline__ float dot4(float4 a, float4 b, float acc) {
    acc = fmaf(a.x, b.x, acc);
    acc = fmaf(a.y, b.y, acc);
    acc = fmaf(a.z, b.z, acc);
    return fmaf(a.w, b.w, acc);
}

__global__ void __launch_bounds__(BLOCK_THREADS)
force_agg_300(const float* __restrict__ hess,
              const float* __restrict__ ns,
              float* __restrict__ out)
{
    constexpr int NCH = D300 / 4;           // 75 float4 chunks per row

    const int m    = blockIdx.x / 5;
    const int tile = blockIdx.x - m * 5;
    const int row0 = tile << 6;             // 64-row tiles; tile 4 = rows 256..299

    const int warp = threadIdx.x >> 5;
    const int lane = threadIdx.x & 31;

    // ns chunks for this lane — reused by all rows this warp touches.
    const float4* ns4 = (const float4*)(ns + (size_t)m * D300);
    const bool has2 = (lane < NCH - 64);
    const float4 n0 = __ldg(ns4 + lane);
    const float4 n1 = __ldg(ns4 + lane + 32);
    const float4 n2 = has2 ? __ldg(ns4 + lane + 64) : f4z();

    const float* hbase = hess + (size_t)m * D300 * D300;
    float*       omol  = out + (size_t)m * D300;

    // Full tiles: warp owns contiguous rows [row0+8w, row0+8w+8), step 2.
    // Tail tile (44 rows): strided pairs for balance (as R6).
    const bool full = (tile < 4);
    int r, rend, rstep;
    if (full) { r = row0 + (warp << 3); rend = r + 8;               rstep = 2;  }
    else      { r = row0 + (warp << 1); rend = D300;                rstep = 16; }

    // ---- prologue: load current pair ----
    {
        const float* hb = hbase + (size_t)r * D300;
        const float4* h0 = (const float4*)hb;
        const float4* h1 = (const float4*)(hb + D300);
        float4 a0 = __ldcs(h0 + lane);
        float4 b0 = __ldcs(h1 + lane);
        float4 a1 = __ldcs(h0 + lane + 32);
        float4 b1 = __ldcs(h1 + lane + 32);
        float4 a2 = f4z(), b2 = f4z();
        if (has2) { a2 = __ldcs(h0 + lane + 64); b2 = __ldcs(h1 + lane + 64); }

#pragma unroll 1
        for (; r < rend; r += rstep) {
            // ---- prefetch next pair (in flight through FMA/shuffle window) ----
            const int rn = r + rstep;
            const bool more = (rn < rend);
            float4 pa0 = f4z(), pb0 = f4z(), pa1 = f4z(), pb1 = f4z(), pa2 = f4z(), pb2 = f4z();
            if (more) {
                const float* gb = hbase + (size_t)rn * D300;
                const float4* g0 = (const float4*)gb;
                const float4* g1 = (const float4*)(gb + D300);
                pa0 = __ldcs(g0 + lane);
                pb0 = __ldcs(g1 + lane);
                pa1 = __ldcs(g0 + lane + 32);
                pb1 = __ldcs(g1 + lane + 32);
                if (has2) { pa2 = __ldcs(g0 + lane + 64); pb2 = __ldcs(g1 + lane + 64); }
            }

            // ---- compute current pair ----
            float acc0 = dot4(a0, n0, 0.f);
            float acc1 = dot4(b0, n0, 0.f);
            acc0 = dot4(a1, n1, acc0);
            acc1 = dot4(b1, n1, acc1);
            acc0 = dot4(a2, n2, acc0);
            acc1 = dot4(b2, n2, acc1);

            // ---- 6-shuffle paired reduction: lane0 -> r, lane16 -> r+1 ----
            acc0 += __shfl_xor_sync(0xffffffffu, acc0, 16);
            acc1 += __shfl_xor_sync(0xffffffffu, acc1, 16);
            float v = (lane & 16) ? acc1 : acc0;
            v += __shfl_xor_sync(0xffffffffu, v, 8);
            v += __shfl_xor_sync(0xffffffffu, v, 4);
            v += __shfl_xor_sync(0xffffffffu, v, 2);
            v += __shfl_xor_sync(0xffffffffu, v, 1);
            if (lane == 0)       omol[r]     = v;
            else if (lane == 16) omol[r + 1] = v;

            // ---- rotate pipeline ----
            a0 = pa0; b0 = pb0; a1 = pa1; b1 = pb1; a2 = pa2; b2 = pb2;
        }
    }
}

// Generic fallback for unexpected D (runtime loop bounds, smem-staged ns).
__global__ void __launch_bounds__(BLOCK_THREADS)
force_agg_generic(const float* __restrict__ hess,
                  const float* __restrict__ ns,
                  float* __restrict__ out,
                  int D, int tiles_per_mol, int rows_per_tile)
{
    extern __shared__ __align__(16) float s_ns[];

    const int m    = blockIdx.x / tiles_per_mol;
    const int tile = blockIdx.x - m * tiles_per_mol;
    const int row0 = tile * rows_per_tile;

    const float* nsm = ns + (size_t)m * D;
    const int nch = D >> 2;
    for (int i = threadIdx.x; i < nch; i += BLOCK_THREADS)
        ((float4*)s_ns)[i] = ((const float4*)nsm)[i];
    for (int i = nch * 4 + threadIdx.x; i < D; i += BLOCK_THREADS)
        s_ns[i] = nsm[i];
    __syncthreads();

    const int warp  = threadIdx.x >> 5;
    const int lane  = threadIdx.x & 31;
    const int nwrps = BLOCK_THREADS >> 5;

    const float4* s4    = (const float4*)s_ns;
    const float*  hbase = hess + (size_t)m * D * D;

    int rend = row0 + rows_per_tile;
    if (rend > D) rend = D;

    for (int r = row0 + warp; r < rend; r += nwrps) {
        const float4* hrow = (const float4*)(hbase + (size_t)r * D);
        float acc = 0.0f;
        for (int c = lane; c < nch; c += 32) {
            const float4 h = __ldcs(hrow + c);
            const float4 n = s4[c];
            acc = fmaf(h.x, n.x, acc);
            acc = fmaf(h.y, n.y, acc);
            acc = fmaf(h.z, n.z, acc);
            acc = fmaf(h.w, n.w, acc);
        }
        for (int c = nch * 4 + lane; c < D; c += 32)
            acc = fmaf(hbase[(size_t)r * D + c], s_ns[c], acc);
#pragma unroll
        for (int off = 16; off; off >>= 1)
            acc += __shfl_xor_sync(0xffffffffu, acc, off);
        if (lane == 0)
            out[(size_t)m * D + r] = acc;
    }
}

extern "C" void kernel_launch(void* const* d_in, const int* in_sizes, int n_in,
                              void* d_out, int out_size)
{
    // Input order: ns [M*N_AT,3] f32, hess [M*D,D] f32, idx_m i32, n_atoms [M] i32
    const float* ns   = (const float*)d_in[0];
    const float* hess = (const float*)d_in[1];
    float*       out  = (float*)d_out;

    const int M = in_sizes[3];
    const int D = (int)((long long)in_sizes[0] / M);

    if (D == 300) {
        force_agg_300<<<(unsigned)(M * 5), BLOCK_THREADS>>>(hess, ns, out);
    } else {
        const int rows = 64;
        const int tiles = (D + rows - 1) / rows;
        const size_t shmem = (size_t)((D + 3) / 4) * 16;
        force_agg_generic<<<(unsigned)(M * tiles), BLOCK_THREADS, shmem>>>(hess, ns, out, D, tiles, rows);
    }
}